// round 10
// baseline (speedup 1.0000x reference)
#include <cuda_runtime.h>
#include <cuda_bf16.h>
#include <cstdint>
#include <cstddef>

// LSTM encoder: B=128, T=2048, I=64, H=128
// out[0 : B*H) = h_last ; out[B*H : ...) = encoded [B,T,H]
constexpr int B = 128;
constexpr int T = 2048;
constexpr int I = 64;
constexpr int H = 128;
constexpr int G = 4 * H;              // 512 gates
constexpr int KREG = 96;              // W_hh k-values in registers per gate
constexpr int NP   = KREG / 2;        // 48 f32x2 pairs per gate
constexpr int NQR  = KREG / 4;        // 24 register h-quads
constexpr int NQ_SM = (H - KREG) / 4; // 8 smem h-quads

constexpr int NTILES = (B * T) / 64;  // 4096 M-tiles for xproj
constexpr int NCTA_X = 148;           // persistent xproj CTAs

__device__ float g_xp[(size_t)B * T * G + 2 * G];   // padded for overread
__device__ __nv_bfloat16 g_whi[G * I];              // W_ih hi split
__device__ __nv_bfloat16 g_wlo[G * I];              // W_ih lo split

__device__ __forceinline__ void fma2(unsigned long long& d,
                                     unsigned long long a,
                                     unsigned long long b) {
    asm("fma.rn.f32x2 %0, %1, %2, %0;" : "+l"(d) : "l"(a), "l"(b));
}
__device__ __forceinline__ float pair_sum(unsigned long long v) {
    return __uint_as_float((unsigned)v) + __uint_as_float((unsigned)(v >> 32));
}
__device__ __forceinline__ float sig_f(float x) {
    return __fdividef(1.f, 1.f + __expf(-x));
}
__device__ __forceinline__ float tanh_f(float x) {
    return 1.f - 2.f * __fdividef(1.f, 1.f + __expf(2.f * x));
}
__device__ __forceinline__ void cpasync8(uint32_t smem_addr, const void* gptr) {
    asm volatile("cp.async.ca.shared.global [%0], [%1], 8;\n"
                 :: "r"(smem_addr), "l"(gptr) : "memory");
}
__device__ __forceinline__ void cpasync16(uint32_t smem_addr, const void* gptr) {
    asm volatile("cp.async.cg.shared.global [%0], [%1], 16;\n"
                 :: "r"(smem_addr), "l"(gptr) : "memory");
}
__device__ __forceinline__ uint32_t sw128(uint32_t off) {
    return off ^ ((off >> 3) & 0x70);
}
__device__ __forceinline__ void ldsm_x4(uint32_t* r, uint32_t addr) {
    asm volatile("ldmatrix.sync.aligned.m8n8.x4.shared.b16 {%0,%1,%2,%3}, [%4];"
                 : "=r"(r[0]), "=r"(r[1]), "=r"(r[2]), "=r"(r[3]) : "r"(addr));
}
__device__ __forceinline__ void ldsm_x2(uint32_t* r, uint32_t addr) {
    asm volatile("ldmatrix.sync.aligned.m8n8.x2.shared.b16 {%0,%1}, [%2];"
                 : "=r"(r[0]), "=r"(r[1]) : "r"(addr));
}
__device__ __forceinline__ void mma_bf16(float* c, const uint32_t* a,
                                         const uint32_t* b) {
    asm volatile(
        "mma.sync.aligned.m16n8k16.row.col.f32.bf16.bf16.f32 "
        "{%0,%1,%2,%3}, {%4,%5,%6,%7}, {%8,%9}, {%0,%1,%2,%3};"
        : "+f"(c[0]), "+f"(c[1]), "+f"(c[2]), "+f"(c[3])
        : "r"(a[0]), "r"(a[1]), "r"(a[2]), "r"(a[3]), "r"(b[0]), "r"(b[1]));
}

// ---------------------------------------------------------------------------
// Prep: split W_ih into bf16 hi/lo.
// ---------------------------------------------------------------------------
__global__ void wsplit_kernel(const float* __restrict__ Wih) {
    int i = blockIdx.x * blockDim.x + threadIdx.x;   // 32768 total
    float w = Wih[i];
    __nv_bfloat16 h = __float2bfloat16_rn(w);
    g_whi[i] = h;
    g_wlo[i] = __float2bfloat16_rn(w - __bfloat162float(h));
}

// ---------------------------------------------------------------------------
// x_proj via mma.sync, PERSISTENT: 148 CTAs, W loaded once, ~28 tiles each.
// (unchanged from R9)
// ---------------------------------------------------------------------------
constexpr int SM_BIAS = 0;            // 512 floats (2 KB)
constexpr int SM_RAW  = 2048;         // 64 x 64 fp32 = 16 KB
constexpr int SM_AHI  = 18432;        // 64 rows x 128B = 8 KB (SW128)
constexpr int SM_ALO  = 26624;        // 8 KB
constexpr int SM_BHI  = 34816;        // 512 rows x 128B = 64 KB
constexpr int SM_BLO  = 100352;       // 64 KB
constexpr int SMEM_TC = 165888;       // 162 KB

__global__ void __launch_bounds__(256, 1) xproj_tc_kernel(
    const float* __restrict__ in,
    const float* __restrict__ bih,
    const float* __restrict__ bhh)
{
    extern __shared__ char sm[];
    const int t    = threadIdx.x;
    const int lane = t & 31;
    const int wid  = t >> 5;
    const uint32_t smb = (uint32_t)__cvta_generic_to_shared(sm);
    float* bias_s = (float*)(sm + SM_BIAS);
    float* raw_s  = (float*)(sm + SM_RAW);

    {
        const uint4* shi = (const uint4*)g_whi;
        const uint4* slo = (const uint4*)g_wlo;
#pragma unroll
        for (int it = 0; it < 16; it++) {
            int u = t + it * 256;
            int row = u >> 3, ch = u & 7;
            uint32_t off = sw128(row * 128 + ch * 16);
            *(uint4*)(sm + SM_BHI + off) = shi[u];
            *(uint4*)(sm + SM_BLO + off) = slo[u];
        }
    }
    for (int u = t; u < G; u += 256) bias_s[u] = bih[u] + bhh[u];

    const int wm = wid >> 2, wn = wid & 3;
    const int mbase = wm * 32, nbase = wn * 128;
    const uint32_t a_row  = lane & 15;
    const uint32_t a_koff = (lane >> 4) << 4;
    const uint32_t b_row  = lane & 7;
    const uint32_t b_koff = ((lane >> 3) & 1) << 4;

    int tile = blockIdx.x;
    if (tile < NTILES) {
        const char* src = (const char*)(in + (size_t)tile * 64 * I) + t * 16;
#pragma unroll
        for (int i = 0; i < 4; i++)
            cpasync16(smb + SM_RAW + t * 16 + i * 4096, src + (size_t)i * 4096);
    }
    asm volatile("cp.async.commit_group;\n" ::: "memory");

    for (; tile < NTILES; tile += NCTA_X) {
        const size_t m0 = (size_t)tile * 64;
        asm volatile("cp.async.wait_group 0;\n" ::: "memory");
        __syncthreads();

        {
            const int row = t >> 2, q = t & 3;
            const float4* src = (const float4*)(raw_s + row * I + q * 16);
#pragma unroll
            for (int i = 0; i < 4; i++) {
                float4 v = src[i];
                __nv_bfloat16 h0 = __float2bfloat16_rn(v.x);
                __nv_bfloat16 h1 = __float2bfloat16_rn(v.y);
                __nv_bfloat16 h2 = __float2bfloat16_rn(v.z);
                __nv_bfloat16 h3 = __float2bfloat16_rn(v.w);
                __nv_bfloat162 hp0, hp1, lp0, lp1;
                hp0.x = h0; hp0.y = h1; hp1.x = h2; hp1.y = h3;
                lp0.x = __float2bfloat16_rn(v.x - __bfloat162float(h0));
                lp0.y = __float2bfloat16_rn(v.y - __bfloat162float(h1));
                lp1.x = __float2bfloat16_rn(v.z - __bfloat162float(h2));
                lp1.y = __float2bfloat16_rn(v.w - __bfloat162float(h3));
                uint32_t b0 = row * 128 + q * 32 + i * 8;
                *(uint32_t*)(sm + SM_AHI + sw128(b0))     = *(uint32_t*)&hp0;
                *(uint32_t*)(sm + SM_AHI + sw128(b0 + 4)) = *(uint32_t*)&hp1;
                *(uint32_t*)(sm + SM_ALO + sw128(b0))     = *(uint32_t*)&lp0;
                *(uint32_t*)(sm + SM_ALO + sw128(b0 + 4)) = *(uint32_t*)&lp1;
            }
        }
        __syncthreads();

        if (tile + NCTA_X < NTILES) {
            const char* src =
                (const char*)(in + (size_t)(tile + NCTA_X) * 64 * I) + t * 16;
#pragma unroll
            for (int i = 0; i < 4; i++)
                cpasync16(smb + SM_RAW + t * 16 + i * 4096, src + (size_t)i * 4096);
        }
        asm volatile("cp.async.commit_group;\n" ::: "memory");

        float acc[2][16][4];
#pragma unroll
        for (int mt = 0; mt < 2; mt++)
#pragma unroll
            for (int nt = 0; nt < 16; nt++)
#pragma unroll
                for (int r = 0; r < 4; r++) acc[mt][nt][r] = 0.f;

#pragma unroll
        for (int pass = 0; pass < 3; pass++) {
            const uint32_t Ab = smb + (pass == 2 ? SM_ALO : SM_AHI);
            const uint32_t Bb = smb + (pass == 1 ? SM_BLO : SM_BHI);
#pragma unroll
            for (int ks = 0; ks < 4; ks++) {
                uint32_t afr[2][4];
#pragma unroll
                for (int mt = 0; mt < 2; mt++) {
                    uint32_t off = (mbase + mt * 16 + a_row) * 128 + ks * 32 + a_koff;
                    ldsm_x4(afr[mt], Ab + sw128(off));
                }
#pragma unroll
                for (int nt = 0; nt < 16; nt++) {
                    uint32_t boff = (nbase + nt * 8 + b_row) * 128 + ks * 32 + b_koff;
                    uint32_t bfr[2];
                    ldsm_x2(bfr, Bb + sw128(boff));
                    mma_bf16(acc[0][nt], afr[0], bfr);
                    mma_bf16(acc[1][nt], afr[1], bfr);
                }
            }
        }

        {
            const int r0 = lane >> 2;
            const int cq = 2 * (lane & 3);
#pragma unroll
            for (int mt = 0; mt < 2; mt++) {
                size_t row = m0 + mbase + mt * 16 + r0;
#pragma unroll
                for (int nt = 0; nt < 16; nt++) {
                    int col = nbase + nt * 8 + cq;
                    float b0 = bias_s[col], b1 = bias_s[col + 1];
                    *(float2*)(g_xp + row * G + col) =
                        make_float2(acc[mt][nt][0] + b0, acc[mt][nt][1] + b1);
                    *(float2*)(g_xp + (row + 8) * G + col) =
                        make_float2(acc[mt][nt][2] + b0, acc[mt][nt][3] + b1);
                }
            }
        }
        __syncthreads();
    }
}

// ---------------------------------------------------------------------------
// Recurrence: 1 CTA per TWO batch rows (weights shared!), 256 threads.
// Half A (tid<128, j=tid): rows j (i), j+128 (f) for both batch rows; owns c.
// Half B (j=tid-128):      rows j+256 (g), j+384 (o); sends (tanh g, sig o).
// KREG=96 in registers (2x48 ull), 32 k-values in smem; per-step weight
// traffic amortized over 2 rows; serial tail paid once per 2 rows.
// ---------------------------------------------------------------------------
__global__ void __launch_bounds__(256, 1) lstm_kernel(
    const float* __restrict__ h0,
    const float* __restrict__ c0,
    const float* __restrict__ Whh,
    float* __restrict__ out)
{
    extern __shared__ float smem[];
    ulonglong2* Ws2  = (ulonglong2*)smem;            // [NQ_SM][G] quads, 64 KB
    float*      hbuf = smem + NQ_SM * G * 4;         // 4 x 128 (dbuf x row)
    float2*     ex_s = (float2*)(hbuf + 4 * H);      // 2 x 128 float2
    float*      xb   = (float*)(ex_s + 2 * H);       // 4 stages x 2 rows x G

    const int tid  = threadIdx.x;
    const int half = tid >> 7;
    const int j    = tid & 127;
    const int g0   = (half << 8) + j;    // i (A) / g (B)
    const int g1   = g0 + 128;           // f (A) / o (B)
    const int b0r  = blockIdx.x * 2;
    const int b1r  = b0r + 1;

    const float aa = half ? -2.f : 1.f;
    const float bb = half ?  2.f : -1.f;
    const float cc = half ?  1.f : 0.f;

    {   // smem weight slice, k in [KREG,128)
        const ulonglong2* r0 = (const ulonglong2*)(Whh + (size_t)g0 * H + KREG);
        const ulonglong2* r1 = (const ulonglong2*)(Whh + (size_t)g1 * H + KREG);
#pragma unroll
        for (int q = 0; q < NQ_SM; q++) {
            Ws2[q * G + g0] = r0[q];
            Ws2[q * G + g1] = r1[q];
        }
    }

    unsigned long long w0[NP], w1[NP];
    {
        const unsigned long long* r0 = (const unsigned long long*)(Whh + (size_t)g0 * H);
        const unsigned long long* r1 = (const unsigned long long*)(Whh + (size_t)g1 * H);
#pragma unroll
        for (int i = 0; i < NP; i++) { w0[i] = r0[i]; w1[i] = r1[i]; }
    }

    float cA = 0.f, cB = 0.f, hlA = 0.f, hlB = 0.f;
    if (half == 0) {
        cA = c0[b0r * H + j];
        cB = c0[b1r * H + j];
        hbuf[0 * H + j] = h0[b0r * H + j];     // buf0 row0
        hbuf[1 * H + j] = h0[b1r * H + j];     // buf0 row1
    }

    // x ring: stage s, row r at xb + (s*2+r)*G; thread covers 8 B.
    const char* gx0 = (const char*)(g_xp + (size_t)b0r * T * G + tid * 2);
    const char* gx1 = (const char*)(g_xp + (size_t)b1r * T * G + tid * 2);
    const uint32_t xbb = (uint32_t)__cvta_generic_to_shared(xb) + tid * 8u;

    cpasync8(xbb + (0 * 2 + 0) * G * 4, gx0);
    cpasync8(xbb + (0 * 2 + 1) * G * 4, gx1);
    asm volatile("cp.async.commit_group;\n" ::: "memory");
    cpasync8(xbb + (1 * 2 + 0) * G * 4, gx0 + (size_t)G * 4);
    cpasync8(xbb + (1 * 2 + 1) * G * 4, gx1 + (size_t)G * 4);
    asm volatile("cp.async.commit_group;\n" ::: "memory");
    gx0 += (size_t)G * 8; gx1 += (size_t)G * 8;
    asm volatile("cp.async.wait_group 0;\n" ::: "memory");

    __syncthreads();

    float* enc0 = out + (size_t)B * H + (size_t)b0r * T * H;
    float* enc1 = out + (size_t)B * H + (size_t)b1r * T * H;

    auto step = [&](int t, int rdb, int wrb) {
        cpasync8(xbb + (((t + 2) & 3) * 2 + 0) * G * 4, gx0);
        cpasync8(xbb + (((t + 2) & 3) * 2 + 1) * G * 4, gx1);
        gx0 += (size_t)G * 4; gx1 += (size_t)G * 4;
        asm volatile("cp.async.commit_group;\n" ::: "memory");

        unsigned long long A0 = 0, A1 = 0, B0 = 0, B1 = 0;
        unsigned long long C0 = 0, C1 = 0, D0 = 0, D1 = 0;
        const ulonglong2* h2a = (const ulonglong2*)(hbuf + rdb * 2 * H);
        const ulonglong2* h2b = (const ulonglong2*)(hbuf + rdb * 2 * H + H);

#pragma unroll
        for (int q = 0; q < NQR; q++) {              // k in [0,96)
            ulonglong2 ha = h2a[q];
            ulonglong2 hb = h2b[q];
            fma2(A0, w0[2 * q],     ha.x);
            fma2(A1, w0[2 * q + 1], ha.y);
            fma2(B0, w1[2 * q],     ha.x);
            fma2(B1, w1[2 * q + 1], ha.y);
            fma2(C0, w0[2 * q],     hb.x);
            fma2(C1, w0[2 * q + 1], hb.y);
            fma2(D0, w1[2 * q],     hb.x);
            fma2(D1, w1[2 * q + 1], hb.y);
        }
#pragma unroll
        for (int q = 0; q < NQ_SM; q++) {            // k in [96,128)
            ulonglong2 ha = h2a[NQR + q];
            ulonglong2 hb = h2b[NQR + q];
            ulonglong2 wa = Ws2[q * G + g0];
            ulonglong2 wb = Ws2[q * G + g1];
            fma2(A0, wa.x, ha.x);
            fma2(A1, wa.y, ha.y);
            fma2(B0, wb.x, ha.x);
            fma2(B1, wb.y, ha.y);
            fma2(C0, wa.x, hb.x);
            fma2(C1, wa.y, hb.y);
            fma2(D0, wb.x, hb.x);
            fma2(D1, wb.y, hb.y);
        }

        const float* xr0 = xb + ((t & 3) * 2 + 0) * G;
        const float* xr1 = xb + ((t & 3) * 2 + 1) * G;
        float pA0 = pair_sum(A0) + pair_sum(A1) + xr0[g0];
        float pA1 = pair_sum(B0) + pair_sum(B1) + xr0[g1];
        float pB0 = pair_sum(C0) + pair_sum(C1) + xr1[g0];
        float pB1 = pair_sum(D0) + pair_sum(D1) + xr1[g1];

        // per-half branchless activations (A: sig/sig, B: tanh/sig), per row
        float vA0 = fmaf(aa, __fdividef(1.f, 1.f + __expf(bb * pA0)), cc);
        float vA1 = sig_f(pA1);
        float vB0 = fmaf(aa, __fdividef(1.f, 1.f + __expf(bb * pB0)), cc);
        float vB1 = sig_f(pB1);

        if (half) {
            ex_s[j]     = make_float2(vA0, vA1);     // row0: (tanh g, sig o)
            ex_s[j + H] = make_float2(vB0, vB1);     // row1
            asm volatile("bar.arrive 1, 256;" ::: "memory");
        } else {
            asm volatile("bar.sync 1, 256;" ::: "memory");
            float2 go0 = ex_s[j];
            float2 go1 = ex_s[j + H];
            cA = vA1 * cA + vA0 * go0.x;
            cB = vB1 * cB + vB0 * go1.x;
            float hn0 = go0.y * tanh_f(cA);
            float hn1 = go1.y * tanh_f(cB);
            hbuf[wrb * 2 * H + j]     = hn0;
            hbuf[wrb * 2 * H + H + j] = hn1;
            enc0[(size_t)t * H + j] = hn0;
            enc1[(size_t)t * H + j] = hn1;
            hlA = hn0; hlB = hn1;
        }

        asm volatile("cp.async.wait_group 1;\n" ::: "memory");
        __syncthreads();
    };

    for (int t = 0; t < T; t += 2) {
        step(t,     0, 1);
        step(t + 1, 1, 0);
    }

    if (half == 0) {
        out[b0r * H + j] = hlA;
        out[b1r * H + j] = hlB;
    }
}

// ---------------------------------------------------------------------------
extern "C" void kernel_launch(void* const* d_in, const int* in_sizes, int n_in,
                              void* d_out, int out_size) {
    const float* input = (const float*)d_in[0];
    const float* h0    = (const float*)d_in[1];
    const float* c0    = (const float*)d_in[2];
    const float* Wih   = (const float*)d_in[3];
    const float* Whh   = (const float*)d_in[4];
    const float* bih   = (const float*)d_in[5];
    const float* bhh   = (const float*)d_in[6];
    float* out = (float*)d_out;

    constexpr int SMEM2 = (NQ_SM * G * 4 + 4 * H) * (int)sizeof(float)
                        + 2 * H * (int)sizeof(float2)
                        + 4 * 2 * G * (int)sizeof(float);   // 86016 B
    cudaFuncSetAttribute(lstm_kernel,
                         cudaFuncAttributeMaxDynamicSharedMemorySize, SMEM2);
    cudaFuncSetAttribute(xproj_tc_kernel,
                         cudaFuncAttributeMaxDynamicSharedMemorySize, SMEM_TC);

    wsplit_kernel<<<(G * I) / 256, 256>>>(Wih);
    xproj_tc_kernel<<<NCTA_X, 256, SMEM_TC>>>(input, bih, bhh);
    lstm_kernel<<<B / 2, 256, SMEM2>>>(h0, c0, Whh, out);
}

// round 11
// speedup vs baseline: 1.4850x; 1.4850x over previous
#include <cuda_runtime.h>
#include <cuda_bf16.h>
#include <cstdint>
#include <cstddef>

// LSTM encoder: B=128, T=2048, I=64, H=128
// out[0 : B*H) = h_last ; out[B*H : ...) = encoded [B,T,H]
constexpr int B = 128;
constexpr int T = 2048;
constexpr int I = 64;
constexpr int H = 128;
constexpr int G = 4 * H;              // 512 gates
constexpr int KREG = 104;             // W_hh k-values in registers per gate
constexpr int NP   = KREG / 2;        // 52 f32x2 pairs per gate
constexpr int NQR  = KREG / 4;        // 26 register h-quads
constexpr int NQ_SM = (H - KREG) / 4; // 6 smem h-quads

constexpr int NTILES = (B * T) / 64;  // 4096 M-tiles for xproj
constexpr int NCTA_X = 148;           // persistent xproj CTAs

__device__ float g_xp[(size_t)B * T * G + 2 * G];   // padded for overread
__device__ __nv_bfloat16 g_whi[G * I];              // W_ih hi split
__device__ __nv_bfloat16 g_wlo[G * I];              // W_ih lo split

__device__ __forceinline__ void fma2(unsigned long long& d,
                                     unsigned long long a,
                                     unsigned long long b) {
    asm("fma.rn.f32x2 %0, %1, %2, %0;" : "+l"(d) : "l"(a), "l"(b));
}
__device__ __forceinline__ float pair_sum(unsigned long long v) {
    return __uint_as_float((unsigned)v) + __uint_as_float((unsigned)(v >> 32));
}
__device__ __forceinline__ float sig_f(float x) {
    return __fdividef(1.f, 1.f + __expf(-x));
}
__device__ __forceinline__ float tanh_f(float x) {
    return 1.f - 2.f * __fdividef(1.f, 1.f + __expf(2.f * x));
}
__device__ __forceinline__ void cpasync8(uint32_t smem_addr, const void* gptr) {
    asm volatile("cp.async.ca.shared.global [%0], [%1], 8;\n"
                 :: "r"(smem_addr), "l"(gptr) : "memory");
}
__device__ __forceinline__ void cpasync16(uint32_t smem_addr, const void* gptr) {
    asm volatile("cp.async.cg.shared.global [%0], [%1], 16;\n"
                 :: "r"(smem_addr), "l"(gptr) : "memory");
}
__device__ __forceinline__ uint32_t sw128(uint32_t off) {
    return off ^ ((off >> 3) & 0x70);
}
__device__ __forceinline__ void ldsm_x4(uint32_t* r, uint32_t addr) {
    asm volatile("ldmatrix.sync.aligned.m8n8.x4.shared.b16 {%0,%1,%2,%3}, [%4];"
                 : "=r"(r[0]), "=r"(r[1]), "=r"(r[2]), "=r"(r[3]) : "r"(addr));
}
__device__ __forceinline__ void ldsm_x2(uint32_t* r, uint32_t addr) {
    asm volatile("ldmatrix.sync.aligned.m8n8.x2.shared.b16 {%0,%1}, [%2];"
                 : "=r"(r[0]), "=r"(r[1]) : "r"(addr));
}
__device__ __forceinline__ void mma_bf16(float* c, const uint32_t* a,
                                         const uint32_t* b) {
    asm volatile(
        "mma.sync.aligned.m16n8k16.row.col.f32.bf16.bf16.f32 "
        "{%0,%1,%2,%3}, {%4,%5,%6,%7}, {%8,%9}, {%0,%1,%2,%3};"
        : "+f"(c[0]), "+f"(c[1]), "+f"(c[2]), "+f"(c[3])
        : "r"(a[0]), "r"(a[1]), "r"(a[2]), "r"(a[3]), "r"(b[0]), "r"(b[1]));
}

// ---------------------------------------------------------------------------
// Prep: split W_ih into bf16 hi/lo.
// ---------------------------------------------------------------------------
__global__ void wsplit_kernel(const float* __restrict__ Wih) {
    int i = blockIdx.x * blockDim.x + threadIdx.x;   // 32768 total
    float w = Wih[i];
    __nv_bfloat16 h = __float2bfloat16_rn(w);
    g_whi[i] = h;
    g_wlo[i] = __float2bfloat16_rn(w - __bfloat162float(h));
}

// ---------------------------------------------------------------------------
// x_proj via mma.sync, PERSISTENT: 148 CTAs, W loaded once, ~28 tiles each.
// Per tile: D[64, 512] = A(64x64) W^T in 3 bf16 passes, fp32 acc.
// Raw A tile staged by cp.async during previous tile's MMA.
// ---------------------------------------------------------------------------
constexpr int SM_BIAS = 0;            // 512 floats (2 KB)
constexpr int SM_RAW  = 2048;         // 64 x 64 fp32 = 16 KB
constexpr int SM_AHI  = 18432;        // 64 rows x 128B = 8 KB (SW128)
constexpr int SM_ALO  = 26624;        // 8 KB
constexpr int SM_BHI  = 34816;        // 512 rows x 128B = 64 KB
constexpr int SM_BLO  = 100352;       // 64 KB
constexpr int SMEM_TC = 165888;       // 162 KB

__global__ void __launch_bounds__(256, 1) xproj_tc_kernel(
    const float* __restrict__ in,
    const float* __restrict__ bih,
    const float* __restrict__ bhh)
{
    extern __shared__ char sm[];
    const int t    = threadIdx.x;
    const int lane = t & 31;
    const int wid  = t >> 5;
    const uint32_t smb = (uint32_t)__cvta_generic_to_shared(sm);
    float* bias_s = (float*)(sm + SM_BIAS);
    float* raw_s  = (float*)(sm + SM_RAW);

    // one-time: W tiles (hi/lo) into SW128 smem
    {
        const uint4* shi = (const uint4*)g_whi;
        const uint4* slo = (const uint4*)g_wlo;
#pragma unroll
        for (int it = 0; it < 16; it++) {
            int u = t + it * 256;
            int row = u >> 3, ch = u & 7;
            uint32_t off = sw128(row * 128 + ch * 16);
            *(uint4*)(sm + SM_BHI + off) = shi[u];
            *(uint4*)(sm + SM_BLO + off) = slo[u];
        }
    }
    for (int u = t; u < G; u += 256) bias_s[u] = bih[u] + bhh[u];

    const int wm = wid >> 2, wn = wid & 3;
    const int mbase = wm * 32, nbase = wn * 128;
    const uint32_t a_row  = lane & 15;
    const uint32_t a_koff = (lane >> 4) << 4;
    const uint32_t b_row  = lane & 7;
    const uint32_t b_koff = ((lane >> 3) & 1) << 4;

    int tile = blockIdx.x;
    if (tile < NTILES) {
        const char* src = (const char*)(in + (size_t)tile * 64 * I) + t * 16;
#pragma unroll
        for (int i = 0; i < 4; i++)
            cpasync16(smb + SM_RAW + t * 16 + i * 4096, src + (size_t)i * 4096);
    }
    asm volatile("cp.async.commit_group;\n" ::: "memory");

    for (; tile < NTILES; tile += NCTA_X) {
        const size_t m0 = (size_t)tile * 64;
        asm volatile("cp.async.wait_group 0;\n" ::: "memory");
        __syncthreads();                          // raw A visible

        // split raw fp32 -> bf16 hi/lo, SW128
        {
            const int row = t >> 2, q = t & 3;
            const float4* src = (const float4*)(raw_s + row * I + q * 16);
#pragma unroll
            for (int i = 0; i < 4; i++) {
                float4 v = src[i];
                __nv_bfloat16 h0 = __float2bfloat16_rn(v.x);
                __nv_bfloat16 h1 = __float2bfloat16_rn(v.y);
                __nv_bfloat16 h2 = __float2bfloat16_rn(v.z);
                __nv_bfloat16 h3 = __float2bfloat16_rn(v.w);
                __nv_bfloat162 hp0, hp1, lp0, lp1;
                hp0.x = h0; hp0.y = h1; hp1.x = h2; hp1.y = h3;
                lp0.x = __float2bfloat16_rn(v.x - __bfloat162float(h0));
                lp0.y = __float2bfloat16_rn(v.y - __bfloat162float(h1));
                lp1.x = __float2bfloat16_rn(v.z - __bfloat162float(h2));
                lp1.y = __float2bfloat16_rn(v.w - __bfloat162float(h3));
                uint32_t b0 = row * 128 + q * 32 + i * 8;
                *(uint32_t*)(sm + SM_AHI + sw128(b0))     = *(uint32_t*)&hp0;
                *(uint32_t*)(sm + SM_AHI + sw128(b0 + 4)) = *(uint32_t*)&hp1;
                *(uint32_t*)(sm + SM_ALO + sw128(b0))     = *(uint32_t*)&lp0;
                *(uint32_t*)(sm + SM_ALO + sw128(b0 + 4)) = *(uint32_t*)&lp1;
            }
        }
        __syncthreads();                          // AHI/ALO ready; raw free

        // stage next tile's raw A (overlaps MMA + epilogue)
        if (tile + NCTA_X < NTILES) {
            const char* src =
                (const char*)(in + (size_t)(tile + NCTA_X) * 64 * I) + t * 16;
#pragma unroll
            for (int i = 0; i < 4; i++)
                cpasync16(smb + SM_RAW + t * 16 + i * 4096, src + (size_t)i * 4096);
        }
        asm volatile("cp.async.commit_group;\n" ::: "memory");

        float acc[2][16][4];
#pragma unroll
        for (int mt = 0; mt < 2; mt++)
#pragma unroll
            for (int nt = 0; nt < 16; nt++)
#pragma unroll
                for (int r = 0; r < 4; r++) acc[mt][nt][r] = 0.f;

#pragma unroll
        for (int pass = 0; pass < 3; pass++) {
            const uint32_t Ab = smb + (pass == 2 ? SM_ALO : SM_AHI);
            const uint32_t Bb = smb + (pass == 1 ? SM_BLO : SM_BHI);
#pragma unroll
            for (int ks = 0; ks < 4; ks++) {
                uint32_t afr[2][4];
#pragma unroll
                for (int mt = 0; mt < 2; mt++) {
                    uint32_t off = (mbase + mt * 16 + a_row) * 128 + ks * 32 + a_koff;
                    ldsm_x4(afr[mt], Ab + sw128(off));
                }
#pragma unroll
                for (int nt = 0; nt < 16; nt++) {
                    uint32_t boff = (nbase + nt * 8 + b_row) * 128 + ks * 32 + b_koff;
                    uint32_t bfr[2];
                    ldsm_x2(bfr, Bb + sw128(boff));
                    mma_bf16(acc[0][nt], afr[0], bfr);
                    mma_bf16(acc[1][nt], afr[1], bfr);
                }
            }
        }

        // epilogue
        {
            const int r0 = lane >> 2;
            const int cq = 2 * (lane & 3);
#pragma unroll
            for (int mt = 0; mt < 2; mt++) {
                size_t row = m0 + mbase + mt * 16 + r0;
#pragma unroll
                for (int nt = 0; nt < 16; nt++) {
                    int col = nbase + nt * 8 + cq;
                    float b0 = bias_s[col], b1 = bias_s[col + 1];
                    *(float2*)(g_xp + row * G + col) =
                        make_float2(acc[mt][nt][0] + b0, acc[mt][nt][1] + b1);
                    *(float2*)(g_xp + (row + 8) * G + col) =
                        make_float2(acc[mt][nt][2] + b0, acc[mt][nt][3] + b1);
                }
            }
        }
        __syncthreads();        // ldsm reads done before next split overwrites A
    }
}

// ---------------------------------------------------------------------------
// Recurrence: EXACT R8/R6 version (best measured: ~1477 us).
// 1 CTA/batch row, 256 threads, cp.async x ring, single h_s, 2 barriers/step.
// ---------------------------------------------------------------------------
__global__ void __launch_bounds__(256, 1) lstm_kernel(
    const float* __restrict__ h0,
    const float* __restrict__ c0,
    const float* __restrict__ Whh,
    float* __restrict__ out)
{
    extern __shared__ float smem[];
    ulonglong2* Ws2  = (ulonglong2*)smem;              // [NQ_SM][G] quads, 48 KB
    float*      h_s  = smem + NQ_SM * G * 4;           // 128 floats
    float2*     ex_s = (float2*)(h_s + H);             // 128 float2
    float*      xb   = (float*)(ex_s + H);             // 4 * G floats (8 KB)

    const int tid  = threadIdx.x;
    const int half = tid >> 7;
    const int j    = tid & 127;
    const int g0   = (half << 8) + j;    // i (A) / g (B)
    const int g1   = g0 + 128;           // f (A) / o (B)
    const int b    = blockIdx.x;

    const float aa = half ? -2.f : 1.f;
    const float bb = half ?  2.f : -1.f;
    const float cc = half ?  1.f : 0.f;

    {
        const ulonglong2* r0 = (const ulonglong2*)(Whh + (size_t)g0 * H + KREG);
        const ulonglong2* r1 = (const ulonglong2*)(Whh + (size_t)g1 * H + KREG);
#pragma unroll
        for (int q = 0; q < NQ_SM; q++) {
            Ws2[q * G + g0] = r0[q];
            Ws2[q * G + g1] = r1[q];
        }
    }

    unsigned long long w0[NP], w1[NP];
    {
        const unsigned long long* r0 = (const unsigned long long*)(Whh + (size_t)g0 * H);
        const unsigned long long* r1 = (const unsigned long long*)(Whh + (size_t)g1 * H);
#pragma unroll
        for (int i = 0; i < NP; i++) { w0[i] = r0[i]; w1[i] = r1[i]; }
    }

    float c = 0.f, hn_last = 0.f;
    if (half == 0) {
        c = c0[b * H + j];
        h_s[j] = h0[b * H + j];
    }

    const char* gx = (const char*)(g_xp + (size_t)b * T * G + tid * 2);
    const uint32_t xb_base = (uint32_t)__cvta_generic_to_shared(xb) + tid * 8u;

    cpasync8(xb_base + 0 * G * 4, gx);  gx += (size_t)G * 4;
    asm volatile("cp.async.commit_group;\n" ::: "memory");
    cpasync8(xb_base + 1 * G * 4, gx);  gx += (size_t)G * 4;
    asm volatile("cp.async.commit_group;\n" ::: "memory");
    asm volatile("cp.async.wait_group 0;\n" ::: "memory");

    __syncthreads();

    float* enc = out + (size_t)B * H + (size_t)b * T * H;

    for (int t = 0; t < T; t++) {
        cpasync8(xb_base + ((t + 2) & 3) * G * 4, gx);
        gx += (size_t)G * 4;
        asm volatile("cp.async.commit_group;\n" ::: "memory");

        unsigned long long a0 = 0ull, a1 = 0ull, b0 = 0ull, b1 = 0ull;
        const ulonglong2* h2 = (const ulonglong2*)h_s;

#pragma unroll
        for (int q = 0; q < NQR; q++) {
            ulonglong2 hv = h2[q];
            fma2(a0, w0[2 * q],     hv.x);
            fma2(a1, w0[2 * q + 1], hv.y);
            fma2(b0, w1[2 * q],     hv.x);
            fma2(b1, w1[2 * q + 1], hv.y);
        }
#pragma unroll
        for (int q = 0; q < NQ_SM; q++) {
            ulonglong2 hv = h2[NQR + q];
            ulonglong2 wa = Ws2[q * G + g0];
            ulonglong2 wb = Ws2[q * G + g1];
            fma2(a0, wa.x, hv.x);
            fma2(a1, wa.y, hv.y);
            fma2(b0, wb.x, hv.x);
            fma2(b1, wb.y, hv.y);
        }

        const float* xrow = xb + (t & 3) * G;
        float p0 = pair_sum(a0) + pair_sum(a1) + xrow[g0];
        float p1 = pair_sum(b0) + pair_sum(b1) + xrow[g1];

        float v0 = fmaf(aa, __fdividef(1.f, 1.f + __expf(bb * p0)), cc);
        float v1 = sig_f(p1);

        if (half) ex_s[j] = make_float2(v0, v1);
        __syncthreads();

        if (!half) {
            float2 go = ex_s[j];
            c = v1 * c + v0 * go.x;
            float hn = go.y * tanh_f(c);
            h_s[j] = hn;
            enc[(size_t)t * H + j] = hn;
            hn_last = hn;
        }

        asm volatile("cp.async.wait_group 1;\n" ::: "memory");
        __syncthreads();
    }

    if (half == 0) out[b * H + j] = hn_last;
}

// ---------------------------------------------------------------------------
extern "C" void kernel_launch(void* const* d_in, const int* in_sizes, int n_in,
                              void* d_out, int out_size) {
    const float* input = (const float*)d_in[0];
    const float* h0    = (const float*)d_in[1];
    const float* c0    = (const float*)d_in[2];
    const float* Wih   = (const float*)d_in[3];
    const float* Whh   = (const float*)d_in[4];
    const float* bih   = (const float*)d_in[5];
    const float* bhh   = (const float*)d_in[6];
    float* out = (float*)d_out;

    constexpr int SMEM2 = (NQ_SM * G * 4 + H) * (int)sizeof(float)
                        + H * (int)sizeof(float2)
                        + 4 * G * (int)sizeof(float);
    cudaFuncSetAttribute(lstm_kernel,
                         cudaFuncAttributeMaxDynamicSharedMemorySize, SMEM2);
    cudaFuncSetAttribute(xproj_tc_kernel,
                         cudaFuncAttributeMaxDynamicSharedMemorySize, SMEM_TC);

    wsplit_kernel<<<(G * I) / 256, 256>>>(Wih);
    xproj_tc_kernel<<<NCTA_X, 256, SMEM_TC>>>(input, bih, bhh);
    lstm_kernel<<<B, 256, SMEM2>>>(h0, c0, Whh, out);
}

// round 12
// speedup vs baseline: 1.6249x; 1.0942x over previous
#include <cuda_runtime.h>
#include <cuda_bf16.h>
#include <cstdint>
#include <cstddef>

// LSTM encoder: B=128, T=2048, I=64, H=128
// out[0 : B*H) = h_last ; out[B*H : ...) = encoded [B,T,H]
constexpr int B = 128;
constexpr int T = 2048;
constexpr int I = 64;
constexpr int H = 128;
constexpr int G = 4 * H;              // 512 gates
constexpr int KREG = 104;             // W_hh k-values in registers per gate
constexpr int NP   = KREG / 2;        // 52 f32x2 pairs per gate
constexpr int NQR  = KREG / 4;        // 26 register h-quads
constexpr int NQ_SM = (H - KREG) / 4; // 6 smem h-quads

constexpr int NTILES = (B * T) / 64;  // 4096 M-tiles for xproj
constexpr int NCTA_X = 148;           // persistent xproj CTAs

__device__ float g_xp[(size_t)B * T * G + 2 * G];   // padded for overread
__device__ __nv_bfloat16 g_whi[G * I];              // W_ih hi split
__device__ __nv_bfloat16 g_wlo[G * I];              // W_ih lo split

__device__ __forceinline__ void fma2(unsigned long long& d,
                                     unsigned long long a,
                                     unsigned long long b) {
    asm("fma.rn.f32x2 %0, %1, %2, %0;" : "+l"(d) : "l"(a), "l"(b));
}
__device__ __forceinline__ float pair_sum(unsigned long long v) {
    return __uint_as_float((unsigned)v) + __uint_as_float((unsigned)(v >> 32));
}
// HW tanh (MUFU.TANH, sm_75+): 1 instruction, lat ~16, abs err ~1e-4.
__device__ __forceinline__ float tanh_hw(float x) {
    float y;
    asm("tanh.approx.f32 %0, %1;" : "=f"(y) : "f"(x));
    return y;
}
__device__ __forceinline__ float sig_f(float x) {
    return fmaf(0.5f, tanh_hw(0.5f * x), 0.5f);
}
__device__ __forceinline__ void cpasync8(uint32_t smem_addr, const void* gptr) {
    asm volatile("cp.async.ca.shared.global [%0], [%1], 8;\n"
                 :: "r"(smem_addr), "l"(gptr) : "memory");
}
__device__ __forceinline__ void cpasync16(uint32_t smem_addr, const void* gptr) {
    asm volatile("cp.async.cg.shared.global [%0], [%1], 16;\n"
                 :: "r"(smem_addr), "l"(gptr) : "memory");
}
__device__ __forceinline__ uint32_t sw128(uint32_t off) {
    return off ^ ((off >> 3) & 0x70);
}
__device__ __forceinline__ void ldsm_x4(uint32_t* r, uint32_t addr) {
    asm volatile("ldmatrix.sync.aligned.m8n8.x4.shared.b16 {%0,%1,%2,%3}, [%4];"
                 : "=r"(r[0]), "=r"(r[1]), "=r"(r[2]), "=r"(r[3]) : "r"(addr));
}
__device__ __forceinline__ void ldsm_x2(uint32_t* r, uint32_t addr) {
    asm volatile("ldmatrix.sync.aligned.m8n8.x2.shared.b16 {%0,%1}, [%2];"
                 : "=r"(r[0]), "=r"(r[1]) : "r"(addr));
}
__device__ __forceinline__ void mma_bf16(float* c, const uint32_t* a,
                                         const uint32_t* b) {
    asm volatile(
        "mma.sync.aligned.m16n8k16.row.col.f32.bf16.bf16.f32 "
        "{%0,%1,%2,%3}, {%4,%5,%6,%7}, {%8,%9}, {%0,%1,%2,%3};"
        : "+f"(c[0]), "+f"(c[1]), "+f"(c[2]), "+f"(c[3])
        : "r"(a[0]), "r"(a[1]), "r"(a[2]), "r"(a[3]), "r"(b[0]), "r"(b[1]));
}

// ---------------------------------------------------------------------------
// Prep: split W_ih into bf16 hi/lo.
// ---------------------------------------------------------------------------
__global__ void wsplit_kernel(const float* __restrict__ Wih) {
    int i = blockIdx.x * blockDim.x + threadIdx.x;   // 32768 total
    float w = Wih[i];
    __nv_bfloat16 h = __float2bfloat16_rn(w);
    g_whi[i] = h;
    g_wlo[i] = __float2bfloat16_rn(w - __bfloat162float(h));
}

// ---------------------------------------------------------------------------
// x_proj via mma.sync, PERSISTENT: 148 CTAs, W loaded once, ~28 tiles each.
// (unchanged from R11)
// ---------------------------------------------------------------------------
constexpr int SM_BIAS = 0;            // 512 floats (2 KB)
constexpr int SM_RAW  = 2048;         // 64 x 64 fp32 = 16 KB
constexpr int SM_AHI  = 18432;        // 64 rows x 128B = 8 KB (SW128)
constexpr int SM_ALO  = 26624;        // 8 KB
constexpr int SM_BHI  = 34816;        // 512 rows x 128B = 64 KB
constexpr int SM_BLO  = 100352;       // 64 KB
constexpr int SMEM_TC = 165888;       // 162 KB

__global__ void __launch_bounds__(256, 1) xproj_tc_kernel(
    const float* __restrict__ in,
    const float* __restrict__ bih,
    const float* __restrict__ bhh)
{
    extern __shared__ char sm[];
    const int t    = threadIdx.x;
    const int lane = t & 31;
    const int wid  = t >> 5;
    const uint32_t smb = (uint32_t)__cvta_generic_to_shared(sm);
    float* bias_s = (float*)(sm + SM_BIAS);
    float* raw_s  = (float*)(sm + SM_RAW);

    // one-time: W tiles (hi/lo) into SW128 smem
    {
        const uint4* shi = (const uint4*)g_whi;
        const uint4* slo = (const uint4*)g_wlo;
#pragma unroll
        for (int it = 0; it < 16; it++) {
            int u = t + it * 256;
            int row = u >> 3, ch = u & 7;
            uint32_t off = sw128(row * 128 + ch * 16);
            *(uint4*)(sm + SM_BHI + off) = shi[u];
            *(uint4*)(sm + SM_BLO + off) = slo[u];
        }
    }
    for (int u = t; u < G; u += 256) bias_s[u] = bih[u] + bhh[u];

    const int wm = wid >> 2, wn = wid & 3;
    const int mbase = wm * 32, nbase = wn * 128;
    const uint32_t a_row  = lane & 15;
    const uint32_t a_koff = (lane >> 4) << 4;
    const uint32_t b_row  = lane & 7;
    const uint32_t b_koff = ((lane >> 3) & 1) << 4;

    int tile = blockIdx.x;
    if (tile < NTILES) {
        const char* src = (const char*)(in + (size_t)tile * 64 * I) + t * 16;
#pragma unroll
        for (int i = 0; i < 4; i++)
            cpasync16(smb + SM_RAW + t * 16 + i * 4096, src + (size_t)i * 4096);
    }
    asm volatile("cp.async.commit_group;\n" ::: "memory");

    for (; tile < NTILES; tile += NCTA_X) {
        const size_t m0 = (size_t)tile * 64;
        asm volatile("cp.async.wait_group 0;\n" ::: "memory");
        __syncthreads();                          // raw A visible

        // split raw fp32 -> bf16 hi/lo, SW128
        {
            const int row = t >> 2, q = t & 3;
            const float4* src = (const float4*)(raw_s + row * I + q * 16);
#pragma unroll
            for (int i = 0; i < 4; i++) {
                float4 v = src[i];
                __nv_bfloat16 h0 = __float2bfloat16_rn(v.x);
                __nv_bfloat16 h1 = __float2bfloat16_rn(v.y);
                __nv_bfloat16 h2 = __float2bfloat16_rn(v.z);
                __nv_bfloat16 h3 = __float2bfloat16_rn(v.w);
                __nv_bfloat162 hp0, hp1, lp0, lp1;
                hp0.x = h0; hp0.y = h1; hp1.x = h2; hp1.y = h3;
                lp0.x = __float2bfloat16_rn(v.x - __bfloat162float(h0));
                lp0.y = __float2bfloat16_rn(v.y - __bfloat162float(h1));
                lp1.x = __float2bfloat16_rn(v.z - __bfloat162float(h2));
                lp1.y = __float2bfloat16_rn(v.w - __bfloat162float(h3));
                uint32_t b0 = row * 128 + q * 32 + i * 8;
                *(uint32_t*)(sm + SM_AHI + sw128(b0))     = *(uint32_t*)&hp0;
                *(uint32_t*)(sm + SM_AHI + sw128(b0 + 4)) = *(uint32_t*)&hp1;
                *(uint32_t*)(sm + SM_ALO + sw128(b0))     = *(uint32_t*)&lp0;
                *(uint32_t*)(sm + SM_ALO + sw128(b0 + 4)) = *(uint32_t*)&lp1;
            }
        }
        __syncthreads();                          // AHI/ALO ready; raw free

        // stage next tile's raw A (overlaps MMA + epilogue)
        if (tile + NCTA_X < NTILES) {
            const char* src =
                (const char*)(in + (size_t)(tile + NCTA_X) * 64 * I) + t * 16;
#pragma unroll
            for (int i = 0; i < 4; i++)
                cpasync16(smb + SM_RAW + t * 16 + i * 4096, src + (size_t)i * 4096);
        }
        asm volatile("cp.async.commit_group;\n" ::: "memory");

        float acc[2][16][4];
#pragma unroll
        for (int mt = 0; mt < 2; mt++)
#pragma unroll
            for (int nt = 0; nt < 16; nt++)
#pragma unroll
                for (int r = 0; r < 4; r++) acc[mt][nt][r] = 0.f;

#pragma unroll
        for (int pass = 0; pass < 3; pass++) {
            const uint32_t Ab = smb + (pass == 2 ? SM_ALO : SM_AHI);
            const uint32_t Bb = smb + (pass == 1 ? SM_BLO : SM_BHI);
#pragma unroll
            for (int ks = 0; ks < 4; ks++) {
                uint32_t afr[2][4];
#pragma unroll
                for (int mt = 0; mt < 2; mt++) {
                    uint32_t off = (mbase + mt * 16 + a_row) * 128 + ks * 32 + a_koff;
                    ldsm_x4(afr[mt], Ab + sw128(off));
                }
#pragma unroll
                for (int nt = 0; nt < 16; nt++) {
                    uint32_t boff = (nbase + nt * 8 + b_row) * 128 + ks * 32 + b_koff;
                    uint32_t bfr[2];
                    ldsm_x2(bfr, Bb + sw128(boff));
                    mma_bf16(acc[0][nt], afr[0], bfr);
                    mma_bf16(acc[1][nt], afr[1], bfr);
                }
            }
        }

        // epilogue
        {
            const int r0 = lane >> 2;
            const int cq = 2 * (lane & 3);
#pragma unroll
            for (int mt = 0; mt < 2; mt++) {
                size_t row = m0 + mbase + mt * 16 + r0;
#pragma unroll
                for (int nt = 0; nt < 16; nt++) {
                    int col = nbase + nt * 8 + cq;
                    float b0 = bias_s[col], b1 = bias_s[col + 1];
                    *(float2*)(g_xp + row * G + col) =
                        make_float2(acc[mt][nt][0] + b0, acc[mt][nt][1] + b1);
                    *(float2*)(g_xp + (row + 8) * G + col) =
                        make_float2(acc[mt][nt][2] + b0, acc[mt][nt][3] + b1);
                }
            }
        }
        __syncthreads();        // ldsm reads done before next split overwrites A
    }
}

// ---------------------------------------------------------------------------
// Recurrence: R11 structure, activations via HW tanh.approx (MUFU).
// Half A (tid<128, j=tid): rows j (i) and j+128 (f); owns c_j, does update.
// Half B (j=tid-128):      rows j+256 (g) and j+384 (o); sends (tanh g, sig o).
// ---------------------------------------------------------------------------
__global__ void __launch_bounds__(256, 1) lstm_kernel(
    const float* __restrict__ h0,
    const float* __restrict__ c0,
    const float* __restrict__ Whh,
    float* __restrict__ out)
{
    extern __shared__ float smem[];
    ulonglong2* Ws2  = (ulonglong2*)smem;              // [NQ_SM][G] quads, 48 KB
    float*      h_s  = smem + NQ_SM * G * 4;           // 128 floats
    float2*     ex_s = (float2*)(h_s + H);             // 128 float2
    float*      xb   = (float*)(ex_s + H);             // 4 * G floats (8 KB)

    const int tid  = threadIdx.x;
    const int half = tid >> 7;
    const int j    = tid & 127;
    const int g0   = (half << 8) + j;    // i (A) / g (B)
    const int g1   = g0 + 128;           // f (A) / o (B)
    const int b    = blockIdx.x;

    // v0 = ee * tanh_hw(ff * p0) + gg :  A = sigmoid, B = tanh
    const float ee = half ? 1.f : 0.5f;
    const float ff = half ? 1.f : 0.5f;
    const float gg = half ? 0.f : 0.5f;

    {
        const ulonglong2* r0 = (const ulonglong2*)(Whh + (size_t)g0 * H + KREG);
        const ulonglong2* r1 = (const ulonglong2*)(Whh + (size_t)g1 * H + KREG);
#pragma unroll
        for (int q = 0; q < NQ_SM; q++) {
            Ws2[q * G + g0] = r0[q];
            Ws2[q * G + g1] = r1[q];
        }
    }

    unsigned long long w0[NP], w1[NP];
    {
        const unsigned long long* r0 = (const unsigned long long*)(Whh + (size_t)g0 * H);
        const unsigned long long* r1 = (const unsigned long long*)(Whh + (size_t)g1 * H);
#pragma unroll
        for (int i = 0; i < NP; i++) { w0[i] = r0[i]; w1[i] = r1[i]; }
    }

    float c = 0.f, hn_last = 0.f;
    if (half == 0) {
        c = c0[b * H + j];
        h_s[j] = h0[b * H + j];
    }

    const char* gx = (const char*)(g_xp + (size_t)b * T * G + tid * 2);
    const uint32_t xb_base = (uint32_t)__cvta_generic_to_shared(xb) + tid * 8u;

    cpasync8(xb_base + 0 * G * 4, gx);  gx += (size_t)G * 4;
    asm volatile("cp.async.commit_group;\n" ::: "memory");
    cpasync8(xb_base + 1 * G * 4, gx);  gx += (size_t)G * 4;
    asm volatile("cp.async.commit_group;\n" ::: "memory");
    asm volatile("cp.async.wait_group 0;\n" ::: "memory");

    __syncthreads();

    float* enc = out + (size_t)B * H + (size_t)b * T * H;

    for (int t = 0; t < T; t++) {
        cpasync8(xb_base + ((t + 2) & 3) * G * 4, gx);
        gx += (size_t)G * 4;
        asm volatile("cp.async.commit_group;\n" ::: "memory");

        unsigned long long a0 = 0ull, a1 = 0ull, b0 = 0ull, b1 = 0ull;
        const ulonglong2* h2 = (const ulonglong2*)h_s;

#pragma unroll
        for (int q = 0; q < NQR; q++) {
            ulonglong2 hv = h2[q];
            fma2(a0, w0[2 * q],     hv.x);
            fma2(a1, w0[2 * q + 1], hv.y);
            fma2(b0, w1[2 * q],     hv.x);
            fma2(b1, w1[2 * q + 1], hv.y);
        }
#pragma unroll
        for (int q = 0; q < NQ_SM; q++) {
            ulonglong2 hv = h2[NQR + q];
            ulonglong2 wa = Ws2[q * G + g0];
            ulonglong2 wb = Ws2[q * G + g1];
            fma2(a0, wa.x, hv.x);
            fma2(a1, wa.y, hv.y);
            fma2(b0, wb.x, hv.x);
            fma2(b1, wb.y, hv.y);
        }

        const float* xrow = xb + (t & 3) * G;
        float p0 = pair_sum(a0) + pair_sum(a1) + xrow[g0];
        float p1 = pair_sum(b0) + pair_sum(b1) + xrow[g1];

        // A: v0 = sig(i), v1 = sig(f) ; B: v0 = tanh(g), v1 = sig(o)
        float v0 = fmaf(ee, tanh_hw(ff * p0), gg);
        float v1 = sig_f(p1);

        if (half) ex_s[j] = make_float2(v0, v1);
        __syncthreads();

        if (!half) {
            float2 go = ex_s[j];
            c = v1 * c + v0 * go.x;              // sig(f)*c + sig(i)*tanh(g)
            float hn = go.y * tanh_hw(c);
            h_s[j] = hn;
            enc[(size_t)t * H + j] = hn;
            hn_last = hn;
        }

        asm volatile("cp.async.wait_group 1;\n" ::: "memory");
        __syncthreads();
    }

    if (half == 0) out[b * H + j] = hn_last;
}

// ---------------------------------------------------------------------------
extern "C" void kernel_launch(void* const* d_in, const int* in_sizes, int n_in,
                              void* d_out, int out_size) {
    const float* input = (const float*)d_in[0];
    const float* h0    = (const float*)d_in[1];
    const float* c0    = (const float*)d_in[2];
    const float* Wih   = (const float*)d_in[3];
    const float* Whh   = (const float*)d_in[4];
    const float* bih   = (const float*)d_in[5];
    const float* bhh   = (const float*)d_in[6];
    float* out = (float*)d_out;

    constexpr int SMEM2 = (NQ_SM * G * 4 + H) * (int)sizeof(float)
                        + H * (int)sizeof(float2)
                        + 4 * G * (int)sizeof(float);
    cudaFuncSetAttribute(lstm_kernel,
                         cudaFuncAttributeMaxDynamicSharedMemorySize, SMEM2);
    cudaFuncSetAttribute(xproj_tc_kernel,
                         cudaFuncAttributeMaxDynamicSharedMemorySize, SMEM_TC);

    wsplit_kernel<<<(G * I) / 256, 256>>>(Wih);
    xproj_tc_kernel<<<NCTA_X, 256, SMEM_TC>>>(input, bih, bhh);
    lstm_kernel<<<B, 256, SMEM2>>>(h0, c0, Whh, out);
}

// round 13
// speedup vs baseline: 1.7378x; 1.0695x over previous
#include <cuda_runtime.h>
#include <cuda_bf16.h>
#include <cstdint>
#include <cstddef>

// LSTM encoder: B=128, T=2048, I=64, H=128
// out[0 : B*H) = h_last ; out[B*H : ...) = encoded [B,T,H]
constexpr int B = 128;
constexpr int T = 2048;
constexpr int I = 64;
constexpr int H = 128;
constexpr int G = 4 * H;              // 512 gates
constexpr int KREG = 104;             // W_hh k-values in fp32 registers per gate
constexpr int NP   = KREG / 2;        // 52 f32x2 pairs per gate
constexpr int NQR  = KREG / 4;        // 26 register h-quads
constexpr int KSM  = H - KREG;        // 24 k-values in smem (bf16)
constexpr int NCH  = KSM / 8;         // 3 bf16 chunks of 8 k per gate

constexpr int NTILES = (B * T) / 64;  // 4096 M-tiles for xproj
constexpr int NCTA_X = 148;           // persistent xproj CTAs

__device__ float g_xp[(size_t)B * T * G + 2 * G];   // padded for overread
__device__ __nv_bfloat16 g_whi[G * I];              // W_ih hi split
__device__ __nv_bfloat16 g_wlo[G * I];              // W_ih lo split

__device__ __forceinline__ void fma2(unsigned long long& d,
                                     unsigned long long a,
                                     unsigned long long b) {
    asm("fma.rn.f32x2 %0, %1, %2, %0;" : "+l"(d) : "l"(a), "l"(b));
}
__device__ __forceinline__ float pair_sum(unsigned long long v) {
    return __uint_as_float((unsigned)v) + __uint_as_float((unsigned)(v >> 32));
}
// expand packed bf16x2 -> packed f32x2 (bf16 = top 16 bits of fp32)
__device__ __forceinline__ unsigned long long bf2_to_f32x2(uint32_t v) {
    uint32_t lo = v << 16;
    uint32_t hi = v & 0xffff0000u;
    unsigned long long r;
    asm("mov.b64 %0, {%1, %2};" : "=l"(r) : "r"(lo), "r"(hi));
    return r;
}
// HW tanh (MUFU.TANH): 1 instruction, abs err ~1e-4 (validated R12).
__device__ __forceinline__ float tanh_hw(float x) {
    float y;
    asm("tanh.approx.f32 %0, %1;" : "=f"(y) : "f"(x));
    return y;
}
__device__ __forceinline__ float sig_f(float x) {
    return fmaf(0.5f, tanh_hw(0.5f * x), 0.5f);
}
__device__ __forceinline__ void cpasync8(uint32_t smem_addr, const void* gptr) {
    asm volatile("cp.async.ca.shared.global [%0], [%1], 8;\n"
                 :: "r"(smem_addr), "l"(gptr) : "memory");
}
__device__ __forceinline__ void cpasync16(uint32_t smem_addr, const void* gptr) {
    asm volatile("cp.async.cg.shared.global [%0], [%1], 16;\n"
                 :: "r"(smem_addr), "l"(gptr) : "memory");
}
__device__ __forceinline__ uint32_t sw128(uint32_t off) {
    return off ^ ((off >> 3) & 0x70);
}
__device__ __forceinline__ void ldsm_x4(uint32_t* r, uint32_t addr) {
    asm volatile("ldmatrix.sync.aligned.m8n8.x4.shared.b16 {%0,%1,%2,%3}, [%4];"
                 : "=r"(r[0]), "=r"(r[1]), "=r"(r[2]), "=r"(r[3]) : "r"(addr));
}
__device__ __forceinline__ void ldsm_x2(uint32_t* r, uint32_t addr) {
    asm volatile("ldmatrix.sync.aligned.m8n8.x2.shared.b16 {%0,%1}, [%2];"
                 : "=r"(r[0]), "=r"(r[1]) : "r"(addr));
}
__device__ __forceinline__ void mma_bf16(float* c, const uint32_t* a,
                                         const uint32_t* b) {
    asm volatile(
        "mma.sync.aligned.m16n8k16.row.col.f32.bf16.bf16.f32 "
        "{%0,%1,%2,%3}, {%4,%5,%6,%7}, {%8,%9}, {%0,%1,%2,%3};"
        : "+f"(c[0]), "+f"(c[1]), "+f"(c[2]), "+f"(c[3])
        : "r"(a[0]), "r"(a[1]), "r"(a[2]), "r"(a[3]), "r"(b[0]), "r"(b[1]));
}

// ---------------------------------------------------------------------------
// Prep: split W_ih into bf16 hi/lo.
// ---------------------------------------------------------------------------
__global__ void wsplit_kernel(const float* __restrict__ Wih) {
    int i = blockIdx.x * blockDim.x + threadIdx.x;   // 32768 total
    float w = Wih[i];
    __nv_bfloat16 h = __float2bfloat16_rn(w);
    g_whi[i] = h;
    g_wlo[i] = __float2bfloat16_rn(w - __bfloat162float(h));
}

// ---------------------------------------------------------------------------
// x_proj via mma.sync, PERSISTENT: 148 CTAs, W loaded once, ~28 tiles each.
// (unchanged from R12)
// ---------------------------------------------------------------------------
constexpr int SM_BIAS = 0;            // 512 floats (2 KB)
constexpr int SM_RAW  = 2048;         // 64 x 64 fp32 = 16 KB
constexpr int SM_AHI  = 18432;        // 64 rows x 128B = 8 KB (SW128)
constexpr int SM_ALO  = 26624;        // 8 KB
constexpr int SM_BHI  = 34816;        // 512 rows x 128B = 64 KB
constexpr int SM_BLO  = 100352;       // 64 KB
constexpr int SMEM_TC = 165888;       // 162 KB

__global__ void __launch_bounds__(256, 1) xproj_tc_kernel(
    const float* __restrict__ in,
    const float* __restrict__ bih,
    const float* __restrict__ bhh)
{
    extern __shared__ char sm[];
    const int t    = threadIdx.x;
    const int lane = t & 31;
    const int wid  = t >> 5;
    const uint32_t smb = (uint32_t)__cvta_generic_to_shared(sm);
    float* bias_s = (float*)(sm + SM_BIAS);
    float* raw_s  = (float*)(sm + SM_RAW);

    {
        const uint4* shi = (const uint4*)g_whi;
        const uint4* slo = (const uint4*)g_wlo;
#pragma unroll
        for (int it = 0; it < 16; it++) {
            int u = t + it * 256;
            int row = u >> 3, ch = u & 7;
            uint32_t off = sw128(row * 128 + ch * 16);
            *(uint4*)(sm + SM_BHI + off) = shi[u];
            *(uint4*)(sm + SM_BLO + off) = slo[u];
        }
    }
    for (int u = t; u < G; u += 256) bias_s[u] = bih[u] + bhh[u];

    const int wm = wid >> 2, wn = wid & 3;
    const int mbase = wm * 32, nbase = wn * 128;
    const uint32_t a_row  = lane & 15;
    const uint32_t a_koff = (lane >> 4) << 4;
    const uint32_t b_row  = lane & 7;
    const uint32_t b_koff = ((lane >> 3) & 1) << 4;

    int tile = blockIdx.x;
    if (tile < NTILES) {
        const char* src = (const char*)(in + (size_t)tile * 64 * I) + t * 16;
#pragma unroll
        for (int i = 0; i < 4; i++)
            cpasync16(smb + SM_RAW + t * 16 + i * 4096, src + (size_t)i * 4096);
    }
    asm volatile("cp.async.commit_group;\n" ::: "memory");

    for (; tile < NTILES; tile += NCTA_X) {
        const size_t m0 = (size_t)tile * 64;
        asm volatile("cp.async.wait_group 0;\n" ::: "memory");
        __syncthreads();

        {
            const int row = t >> 2, q = t & 3;
            const float4* src = (const float4*)(raw_s + row * I + q * 16);
#pragma unroll
            for (int i = 0; i < 4; i++) {
                float4 v = src[i];
                __nv_bfloat16 h0 = __float2bfloat16_rn(v.x);
                __nv_bfloat16 h1 = __float2bfloat16_rn(v.y);
                __nv_bfloat16 h2 = __float2bfloat16_rn(v.z);
                __nv_bfloat16 h3 = __float2bfloat16_rn(v.w);
                __nv_bfloat162 hp0, hp1, lp0, lp1;
                hp0.x = h0; hp0.y = h1; hp1.x = h2; hp1.y = h3;
                lp0.x = __float2bfloat16_rn(v.x - __bfloat162float(h0));
                lp0.y = __float2bfloat16_rn(v.y - __bfloat162float(h1));
                lp1.x = __float2bfloat16_rn(v.z - __bfloat162float(h2));
                lp1.y = __float2bfloat16_rn(v.w - __bfloat162float(h3));
                uint32_t b0 = row * 128 + q * 32 + i * 8;
                *(uint32_t*)(sm + SM_AHI + sw128(b0))     = *(uint32_t*)&hp0;
                *(uint32_t*)(sm + SM_AHI + sw128(b0 + 4)) = *(uint32_t*)&hp1;
                *(uint32_t*)(sm + SM_ALO + sw128(b0))     = *(uint32_t*)&lp0;
                *(uint32_t*)(sm + SM_ALO + sw128(b0 + 4)) = *(uint32_t*)&lp1;
            }
        }
        __syncthreads();

        if (tile + NCTA_X < NTILES) {
            const char* src =
                (const char*)(in + (size_t)(tile + NCTA_X) * 64 * I) + t * 16;
#pragma unroll
            for (int i = 0; i < 4; i++)
                cpasync16(smb + SM_RAW + t * 16 + i * 4096, src + (size_t)i * 4096);
        }
        asm volatile("cp.async.commit_group;\n" ::: "memory");

        float acc[2][16][4];
#pragma unroll
        for (int mt = 0; mt < 2; mt++)
#pragma unroll
            for (int nt = 0; nt < 16; nt++)
#pragma unroll
                for (int r = 0; r < 4; r++) acc[mt][nt][r] = 0.f;

#pragma unroll
        for (int pass = 0; pass < 3; pass++) {
            const uint32_t Ab = smb + (pass == 2 ? SM_ALO : SM_AHI);
            const uint32_t Bb = smb + (pass == 1 ? SM_BLO : SM_BHI);
#pragma unroll
            for (int ks = 0; ks < 4; ks++) {
                uint32_t afr[2][4];
#pragma unroll
                for (int mt = 0; mt < 2; mt++) {
                    uint32_t off = (mbase + mt * 16 + a_row) * 128 + ks * 32 + a_koff;
                    ldsm_x4(afr[mt], Ab + sw128(off));
                }
#pragma unroll
                for (int nt = 0; nt < 16; nt++) {
                    uint32_t boff = (nbase + nt * 8 + b_row) * 128 + ks * 32 + b_koff;
                    uint32_t bfr[2];
                    ldsm_x2(bfr, Bb + sw128(boff));
                    mma_bf16(acc[0][nt], afr[0], bfr);
                    mma_bf16(acc[1][nt], afr[1], bfr);
                }
            }
        }

        {
            const int r0 = lane >> 2;
            const int cq = 2 * (lane & 3);
#pragma unroll
            for (int mt = 0; mt < 2; mt++) {
                size_t row = m0 + mbase + mt * 16 + r0;
#pragma unroll
                for (int nt = 0; nt < 16; nt++) {
                    int col = nbase + nt * 8 + cq;
                    float b0 = bias_s[col], b1 = bias_s[col + 1];
                    *(float2*)(g_xp + row * G + col) =
                        make_float2(acc[mt][nt][0] + b0, acc[mt][nt][1] + b1);
                    *(float2*)(g_xp + (row + 8) * G + col) =
                        make_float2(acc[mt][nt][2] + b0, acc[mt][nt][3] + b1);
                }
            }
        }
        __syncthreads();
    }
}

// ---------------------------------------------------------------------------
// Recurrence: R12 structure; smem weight slice (k in [104,128)) now bf16,
// expanded to f32x2 on the fly (halves the smem weight wavefronts).
// ---------------------------------------------------------------------------
__global__ void __launch_bounds__(256, 1) lstm_kernel(
    const float* __restrict__ h0,
    const float* __restrict__ c0,
    const float* __restrict__ Whh,
    float* __restrict__ out)
{
    extern __shared__ float smem[];
    // Wsb[ch][g]: uint4 = 8 bf16 weights (k = KREG + 8*ch .. +7) of gate g
    uint4*  Wsb  = (uint4*)smem;                        // 3*512*16 = 24 KB
    float*  h_s  = smem + NCH * G * 4;                  // 128 floats
    float2* ex_s = (float2*)(h_s + H);                  // 128 float2
    float*  xb   = (float*)(ex_s + H);                  // 4 * G floats (8 KB)

    const int tid  = threadIdx.x;
    const int half = tid >> 7;
    const int j    = tid & 127;
    const int g0   = (half << 8) + j;    // i (A) / g (B)
    const int g1   = g0 + 128;           // f (A) / o (B)
    const int b    = blockIdx.x;

    // v0 = ee * tanh_hw(ff * p0) + gg :  A = sigmoid, B = tanh
    const float ee = half ? 1.f : 0.5f;
    const float ff = half ? 1.f : 0.5f;
    const float gg = half ? 0.f : 0.5f;

    {   // build bf16 smem weight slice for this thread's two gates
        const float2* r0 = (const float2*)(Whh + (size_t)g0 * H + KREG);
        const float2* r1 = (const float2*)(Whh + (size_t)g1 * H + KREG);
#pragma unroll
        for (int ch = 0; ch < NCH; ch++) {
            uint32_t p0[4], p1[4];
#pragma unroll
            for (int e = 0; e < 4; e++) {
                float2 wa = r0[ch * 4 + e];
                float2 wb = r1[ch * 4 + e];
                __nv_bfloat162 ba, bbv;
                ba.x  = __float2bfloat16_rn(wa.x);
                ba.y  = __float2bfloat16_rn(wa.y);
                bbv.x = __float2bfloat16_rn(wb.x);
                bbv.y = __float2bfloat16_rn(wb.y);
                p0[e] = *(uint32_t*)&ba;
                p1[e] = *(uint32_t*)&bbv;
            }
            Wsb[ch * G + g0] = make_uint4(p0[0], p0[1], p0[2], p0[3]);
            Wsb[ch * G + g1] = make_uint4(p1[0], p1[1], p1[2], p1[3]);
        }
    }

    unsigned long long w0[NP], w1[NP];
    {
        const unsigned long long* r0 = (const unsigned long long*)(Whh + (size_t)g0 * H);
        const unsigned long long* r1 = (const unsigned long long*)(Whh + (size_t)g1 * H);
#pragma unroll
        for (int i = 0; i < NP; i++) { w0[i] = r0[i]; w1[i] = r1[i]; }
    }

    float c = 0.f, hn_last = 0.f;
    if (half == 0) {
        c = c0[b * H + j];
        h_s[j] = h0[b * H + j];
    }

    const char* gx = (const char*)(g_xp + (size_t)b * T * G + tid * 2);
    const uint32_t xb_base = (uint32_t)__cvta_generic_to_shared(xb) + tid * 8u;

    cpasync8(xb_base + 0 * G * 4, gx);  gx += (size_t)G * 4;
    asm volatile("cp.async.commit_group;\n" ::: "memory");
    cpasync8(xb_base + 1 * G * 4, gx);  gx += (size_t)G * 4;
    asm volatile("cp.async.commit_group;\n" ::: "memory");
    asm volatile("cp.async.wait_group 0;\n" ::: "memory");

    __syncthreads();

    float* enc = out + (size_t)B * H + (size_t)b * T * H;

    for (int t = 0; t < T; t++) {
        cpasync8(xb_base + ((t + 2) & 3) * G * 4, gx);
        gx += (size_t)G * 4;
        asm volatile("cp.async.commit_group;\n" ::: "memory");

        unsigned long long a0 = 0ull, a1 = 0ull, b0 = 0ull, b1 = 0ull;
        const ulonglong2* h2 = (const ulonglong2*)h_s;

#pragma unroll
        for (int q = 0; q < NQR; q++) {               // k in [0,104), fp32 regs
            ulonglong2 hv = h2[q];
            fma2(a0, w0[2 * q],     hv.x);
            fma2(a1, w0[2 * q + 1], hv.y);
            fma2(b0, w1[2 * q],     hv.x);
            fma2(b1, w1[2 * q + 1], hv.y);
        }
#pragma unroll
        for (int ch = 0; ch < NCH; ch++) {            // k in [104,128), bf16 smem
            ulonglong2 hv0 = h2[NQR + 2 * ch];
            ulonglong2 hv1 = h2[NQR + 2 * ch + 1];
            uint4 wa = Wsb[ch * G + g0];
            uint4 wb = Wsb[ch * G + g1];
            fma2(a0, bf2_to_f32x2(wa.x), hv0.x);
            fma2(a1, bf2_to_f32x2(wa.y), hv0.y);
            fma2(a0, bf2_to_f32x2(wa.z), hv1.x);
            fma2(a1, bf2_to_f32x2(wa.w), hv1.y);
            fma2(b0, bf2_to_f32x2(wb.x), hv0.x);
            fma2(b1, bf2_to_f32x2(wb.y), hv0.y);
            fma2(b0, bf2_to_f32x2(wb.z), hv1.x);
            fma2(b1, bf2_to_f32x2(wb.w), hv1.y);
        }

        const float* xrow = xb + (t & 3) * G;
        float p0 = pair_sum(a0) + pair_sum(a1) + xrow[g0];
        float p1 = pair_sum(b0) + pair_sum(b1) + xrow[g1];

        // A: v0 = sig(i), v1 = sig(f) ; B: v0 = tanh(g), v1 = sig(o)
        float v0 = fmaf(ee, tanh_hw(ff * p0), gg);
        float v1 = sig_f(p1);

        if (half) ex_s[j] = make_float2(v0, v1);
        __syncthreads();

        if (!half) {
            float2 go = ex_s[j];
            c = v1 * c + v0 * go.x;              // sig(f)*c + sig(i)*tanh(g)
            float hn = go.y * tanh_hw(c);
            h_s[j] = hn;
            enc[(size_t)t * H + j] = hn;
            hn_last = hn;
        }

        asm volatile("cp.async.wait_group 1;\n" ::: "memory");
        __syncthreads();
    }

    if (half == 0) out[b * H + j] = hn_last;
}

// ---------------------------------------------------------------------------
extern "C" void kernel_launch(void* const* d_in, const int* in_sizes, int n_in,
                              void* d_out, int out_size) {
    const float* input = (const float*)d_in[0];
    const float* h0    = (const float*)d_in[1];
    const float* c0    = (const float*)d_in[2];
    const float* Wih   = (const float*)d_in[3];
    const float* Whh   = (const float*)d_in[4];
    const float* bih   = (const float*)d_in[5];
    const float* bhh   = (const float*)d_in[6];
    float* out = (float*)d_out;

    constexpr int SMEM2 = (NCH * G * 4 + H) * (int)sizeof(float)
                        + H * (int)sizeof(float2)
                        + 4 * G * (int)sizeof(float);       // ~34 KB
    cudaFuncSetAttribute(lstm_kernel,
                         cudaFuncAttributeMaxDynamicSharedMemorySize, SMEM2);
    cudaFuncSetAttribute(xproj_tc_kernel,
                         cudaFuncAttributeMaxDynamicSharedMemorySize, SMEM_TC);

    wsplit_kernel<<<(G * I) / 256, 256>>>(Wih);
    xproj_tc_kernel<<<NCTA_X, 256, SMEM_TC>>>(input, bih, bhh);
    lstm_kernel<<<B, 256, SMEM2>>>(h0, c0, Whh, out);
}